// round 1
// baseline (speedup 1.0000x reference)
#include <cuda_runtime.h>
#include <math.h>

#define BB 16
#define NN 2048
#define CC 128

// ---------------- device scratch (no allocations allowed) ----------------
__device__ float g_Wsym[CC * CC];                 // 64 KB
__device__ float g_G[BB * NN * CC];               // 16 MB  (H @ W_sym)
__device__ float g_part[BB * NN * 16];            // 2 MB   per-(row, col-tile) exp partial sums
__device__ float g_inv[BB * NN];                  // 128 KB 1/rowsum

__device__ __forceinline__ int fxor(int k) {
    // XOR swizzle: conflict-free for both transposing stores (lanes vary k4)
    // and compute loads (lanes vary m). Value in [0,31].
    return ((k >> 2) ^ ((k & 3) << 3));
}

// ---------------- W_sym = 0.5/(sqrt(C)*TAU) * (Wq^T Wk + Wk^T Wq) --------
__global__ void k_wsym(const float* __restrict__ Wq, const float* __restrict__ Wk) {
    int k = blockIdx.x;    // output row
    int c = threadIdx.x;   // output col
    float a1 = 0.f, a2 = 0.f;
    for (int e = 0; e < CC; e++) {
        float wq_k = Wq[e * CC + k];
        float wk_k = Wk[e * CC + k];
        a1 += wq_k * Wk[e * CC + c];
        a2 += wk_k * Wq[e * CC + c];
    }
    const float s = 0.5f / (sqrtf(128.0f) * 1.5f);
    g_Wsym[k * CC + c] = s * (a1 + a2);
}

// ---------------- G = H @ W_sym  (per 128-row tile) ----------------------
// grid: B*N/128 = 256 CTAs, 256 threads, smem = 2 * 64 KB
__global__ void __launch_bounds__(256) k_G(const float* __restrict__ H) {
    extern __shared__ float smem[];
    float* As = smem;             // H tile, k-major with XOR swizzle: As[k*128 + (m^f(k))]
    float* Bs = smem + 128 * 128; // W_sym, already k-major: Bs[k*128 + c]
    int rb  = blockIdx.x;
    int tid = threadIdx.x;

    const float* Hp = H + (size_t)rb * 128 * CC;
    #pragma unroll
    for (int it = 0; it < 16; it++) {
        int flat = it * 256 + tid;
        int m  = flat >> 5;
        int k4 = flat & 31;
        float4 v = *(const float4*)(Hp + m * CC + 4 * k4);
        As[(4 * k4 + 0) * 128 + (m ^ (k4 ^ 0 ))] = v.x;
        As[(4 * k4 + 1) * 128 + (m ^ (k4 ^ 8 ))] = v.y;
        As[(4 * k4 + 2) * 128 + (m ^ (k4 ^ 16))] = v.z;
        As[(4 * k4 + 3) * 128 + (m ^ (k4 ^ 24))] = v.w;
    }
    #pragma unroll
    for (int it = 0; it < 16; it++) {
        int flat = it * 256 + tid;
        int k  = flat >> 5;
        int c4 = flat & 31;
        *(float4*)(Bs + k * 128 + 4 * c4) = *(const float4*)(g_Wsym + k * CC + 4 * c4);
    }
    __syncthreads();

    int rg = tid >> 4;   // 0..15
    int cg = tid & 15;   // 0..15
    float acc[8][8];
    #pragma unroll
    for (int i = 0; i < 8; i++)
        #pragma unroll
        for (int j = 0; j < 8; j++) acc[i][j] = 0.f;

    #pragma unroll 4
    for (int k = 0; k < 128; k++) {
        int f = fxor(k);
        float a[8], b[8];
        #pragma unroll
        for (int i = 0; i < 8; i++) a[i] = As[k * 128 + ((8 * rg + i) ^ f)];
        #pragma unroll
        for (int j = 0; j < 8; j++) b[j] = Bs[k * 128 + cg + 16 * j];
        #pragma unroll
        for (int i = 0; i < 8; i++)
            #pragma unroll
            for (int j = 0; j < 8; j++) acc[i][j] += a[i] * b[j];
    }

    float* Gp = g_G + (size_t)rb * 128 * CC;
    #pragma unroll
    for (int i = 0; i < 8; i++)
        #pragma unroll
        for (int j = 0; j < 8; j++)
            Gp[(8 * rg + i) * CC + cg + 16 * j] = acc[i][j];
}

// ---------------- main: logits tile = G_rows @ H_cols^T, fused epilogue ---
// grid: (ct=16, rt=16, b=16) = 4096 CTAs, 256 threads, smem = 2 * 64 KB
__global__ void __launch_bounds__(256) k_main(const float* __restrict__ H,
                                              const float* __restrict__ Ast,
                                              const float* __restrict__ Mm,
                                              float* __restrict__ out) {
    extern __shared__ float smem[];
    float* As = smem;              // G rows,  k-major XOR
    float* Bs = smem + 128 * 128;  // H rows,  k-major XOR
    int ct = blockIdx.x, rt = blockIdx.y, b = blockIdx.z;
    int tid = threadIdx.x;

    const float* Gp = g_G + ((size_t)(b * NN + rt * 128)) * CC;
    const float* Hp = H   + ((size_t)(b * NN + ct * 128)) * CC;

    #pragma unroll
    for (int it = 0; it < 16; it++) {
        int flat = it * 256 + tid;
        int m  = flat >> 5;
        int k4 = flat & 31;
        float4 va = *(const float4*)(Gp + m * CC + 4 * k4);
        float4 vb = *(const float4*)(Hp + m * CC + 4 * k4);
        As[(4 * k4 + 0) * 128 + (m ^ (k4 ^ 0 ))] = va.x;
        As[(4 * k4 + 1) * 128 + (m ^ (k4 ^ 8 ))] = va.y;
        As[(4 * k4 + 2) * 128 + (m ^ (k4 ^ 16))] = va.z;
        As[(4 * k4 + 3) * 128 + (m ^ (k4 ^ 24))] = va.w;
        Bs[(4 * k4 + 0) * 128 + (m ^ (k4 ^ 0 ))] = vb.x;
        Bs[(4 * k4 + 1) * 128 + (m ^ (k4 ^ 8 ))] = vb.y;
        Bs[(4 * k4 + 2) * 128 + (m ^ (k4 ^ 16))] = vb.z;
        Bs[(4 * k4 + 3) * 128 + (m ^ (k4 ^ 24))] = vb.w;
    }
    __syncthreads();

    int rg = tid >> 4;   // 0..15  -> rows 8*rg .. 8*rg+7
    int cg = tid & 15;   // 0..15  -> cols cg + 16*j
    float acc[8][8];
    #pragma unroll
    for (int i = 0; i < 8; i++)
        #pragma unroll
        for (int j = 0; j < 8; j++) acc[i][j] = 0.f;

    #pragma unroll 4
    for (int k = 0; k < 128; k++) {
        int f = fxor(k);
        float a[8], bb[8];
        #pragma unroll
        for (int i = 0; i < 8; i++) a[i]  = As[k * 128 + ((8 * rg + i)  ^ f)];
        #pragma unroll
        for (int j = 0; j < 8; j++) bb[j] = Bs[k * 128 + ((cg + 16 * j) ^ f)];
        #pragma unroll
        for (int i = 0; i < 8; i++)
            #pragma unroll
            for (int j = 0; j < 8; j++) acc[i][j] += a[i] * bb[j];
    }

    // Epilogue: bias + mask + diag + exp (no max-subtraction: logits are O(1)),
    // write unnormalized exp, accumulate deterministic per-tile row sums.
    int nbase = rt * 128 + 8 * rg;
    int mbase = ct * 128 + cg;
    float rs[8];
    #pragma unroll
    for (int i = 0; i < 8; i++) rs[i] = 0.f;

    #pragma unroll
    for (int i = 0; i < 8; i++) {
        int n = nbase + i;
        const float* Arow = Ast + (size_t)n * NN;
        const float* Mrow = Mm  + (size_t)n * NN;
        float* orow = out + ((size_t)(b * NN + n)) * NN;
        #pragma unroll
        for (int j = 0; j < 8; j++) {
            int m = mbase + 16 * j;
            float e = 0.f;
            if (m != n && Mrow[m] > 0.f)
                e = __expf(acc[i][j] + Arow[m]);   // ETA = 1
            orow[m] = e;
            rs[i] += e;
        }
    }
    // reduce across the 16 lanes sharing this rg (half-warp)
    #pragma unroll
    for (int i = 0; i < 8; i++) {
        #pragma unroll
        for (int off = 8; off > 0; off >>= 1)
            rs[i] += __shfl_down_sync(0xffffffffu, rs[i], off, 16);
    }
    if (cg == 0) {
        #pragma unroll
        for (int i = 0; i < 8; i++)
            g_part[(size_t)(b * NN + nbase + i) * 16 + ct] = rs[i];
    }
}

// ---------------- 1/rowsum ----------------------------------------------
__global__ void k_inv() {
    int r = blockIdx.x * blockDim.x + threadIdx.x;   // 0..BB*NN-1
    float s = 0.f;
    #pragma unroll
    for (int t = 0; t < 16; t++) s += g_part[(size_t)r * 16 + t];
    g_inv[r] = 1.0f / s;
}

// ---------------- normalize in place -------------------------------------
__global__ void k_norm(float* __restrict__ out) {
    size_t idx4 = (size_t)blockIdx.x * blockDim.x + threadIdx.x;  // one float4 each
    size_t row  = idx4 >> 9;            // 512 float4 per 2048-col row
    float inv   = g_inv[row];
    float4 v = ((float4*)out)[idx4];
    v.x *= inv; v.y *= inv; v.z *= inv; v.w *= inv;
    ((float4*)out)[idx4] = v;
}

// ---------------- launch --------------------------------------------------
extern "C" void kernel_launch(void* const* d_in, const int* in_sizes, int n_in,
                              void* d_out, int out_size) {
    const float* H   = (const float*)d_in[0];
    const float* Ast = (const float*)d_in[1];
    const float* Mm  = (const float*)d_in[2];
    const float* Wq  = (const float*)d_in[3];
    const float* Wk  = (const float*)d_in[4];
    float* out = (float*)d_out;

    static bool attr_done = false;
    if (!attr_done) {
        cudaFuncSetAttribute(k_G,    cudaFuncAttributeMaxDynamicSharedMemorySize, 131072);
        cudaFuncSetAttribute(k_main, cudaFuncAttributeMaxDynamicSharedMemorySize, 131072);
        attr_done = true;
    }

    k_wsym<<<CC, CC>>>(Wq, Wk);
    k_G<<<(BB * NN) / 128, 256, 131072>>>(H);
    {
        dim3 grid(NN / 128, NN / 128, BB);   // (ct, rt, b)
        k_main<<<grid, 256, 131072>>>(H, Ast, Mm, out);
    }
    k_inv<<<(BB * NN) / 256, 256>>>();
    k_norm<<<(BB * NN * NN / 4) / 256, 256>>>(out);
}

// round 3
// speedup vs baseline: 3.2566x; 3.2566x over previous
#include <cuda_runtime.h>
#include <cuda_bf16.h>
#include <math.h>
#include <stdint.h>

#define BB 16
#define NN 2048
#define CC 128

// ---------------- device scratch ----------------
__device__ float         g_Wsym[CC * CC];
__device__ __nv_bfloat16 g_Ghi[BB * NN * CC];
__device__ __nv_bfloat16 g_Glo[BB * NN * CC];
__device__ __nv_bfloat16 g_Hhi[BB * NN * CC];
__device__ __nv_bfloat16 g_Hlo[BB * NN * CC];
__device__ float         g_part[(size_t)BB * NN * 64];
__device__ float         g_inv[BB * NN];

// ---------------- helpers ----------------
__device__ __forceinline__ uint32_t smem_u32(const void* p) {
    uint32_t a;
    asm("{ .reg .u64 t; cvta.to.shared.u64 t, %1; cvt.u32.u64 %0, t; }" : "=r"(a) : "l"(p));
    return a;
}

#define LDSM_X4(r0, r1, r2, r3, addr) \
    asm volatile("ldmatrix.sync.aligned.m8n8.x4.shared.b16 {%0,%1,%2,%3}, [%4];" \
        : "=r"(r0), "=r"(r1), "=r"(r2), "=r"(r3) : "r"(addr))

#define MMA16816(d, a, b0, b1) \
    asm volatile("mma.sync.aligned.m16n8k16.row.col.f32.bf16.bf16.f32 " \
        "{%0,%1,%2,%3}, {%4,%5,%6,%7}, {%8,%9}, {%0,%1,%2,%3};" \
        : "+f"((d)[0]), "+f"((d)[1]), "+f"((d)[2]), "+f"((d)[3]) \
        : "r"((a)[0]), "r"((a)[1]), "r"((a)[2]), "r"((a)[3]), "r"(b0), "r"(b1))

// ---------------- W_sym ----------------
__global__ void k_wsym(const float* __restrict__ Wq, const float* __restrict__ Wk) {
    int k = blockIdx.x, c = threadIdx.x;
    float a1 = 0.f, a2 = 0.f;
    for (int e = 0; e < CC; e++) {
        a1 += Wq[e * CC + k] * Wk[e * CC + c];
        a2 += Wk[e * CC + k] * Wq[e * CC + c];
    }
    g_Wsym[k * CC + c] = (0.5f / (sqrtf(128.0f) * 1.5f)) * (a1 + a2);
}

// ---------------- split H into bf16 hi/lo ----------------
__global__ void k_splitH(const float* __restrict__ H) {
    size_t i = ((size_t)blockIdx.x * blockDim.x + threadIdx.x) * 4;
    float4 v = *(const float4*)(H + i);
    float x[4] = {v.x, v.y, v.z, v.w};
    #pragma unroll
    for (int j = 0; j < 4; j++) {
        __nv_bfloat16 h = __float2bfloat16(x[j]);
        g_Hhi[i + j] = h;
        g_Hlo[i + j] = __float2bfloat16(x[j] - __bfloat162float(h));
    }
}

// ---------------- G = H @ W_sym, split output ----------------
__device__ __forceinline__ int fxor(int k) { return ((k >> 2) ^ ((k & 3) << 3)); }

__global__ void __launch_bounds__(256) k_G(const float* __restrict__ H) {
    extern __shared__ float smf[];
    float* As = smf;
    float* Bs = smf + 128 * 128;
    int rb = blockIdx.x, tid = threadIdx.x;
    const float* Hp = H + (size_t)rb * 128 * CC;
    #pragma unroll
    for (int it = 0; it < 16; it++) {
        int flat = it * 256 + tid, m = flat >> 5, k4 = flat & 31;
        float4 v = *(const float4*)(Hp + m * CC + 4 * k4);
        As[(4 * k4 + 0) * 128 + (m ^ (k4 ^ 0 ))] = v.x;
        As[(4 * k4 + 1) * 128 + (m ^ (k4 ^ 8 ))] = v.y;
        As[(4 * k4 + 2) * 128 + (m ^ (k4 ^ 16))] = v.z;
        As[(4 * k4 + 3) * 128 + (m ^ (k4 ^ 24))] = v.w;
    }
    #pragma unroll
    for (int it = 0; it < 16; it++) {
        int flat = it * 256 + tid, k = flat >> 5, c4 = flat & 31;
        *(float4*)(Bs + k * 128 + 4 * c4) = *(const float4*)(g_Wsym + k * CC + 4 * c4);
    }
    __syncthreads();
    int rg = tid >> 4, cg = tid & 15;
    float acc[8][8];
    #pragma unroll
    for (int i = 0; i < 8; i++)
        #pragma unroll
        for (int j = 0; j < 8; j++) acc[i][j] = 0.f;
    #pragma unroll 4
    for (int k = 0; k < 128; k++) {
        int f = fxor(k);
        float a[8], b[8];
        #pragma unroll
        for (int i = 0; i < 8; i++) a[i] = As[k * 128 + ((8 * rg + i) ^ f)];
        #pragma unroll
        for (int j = 0; j < 8; j++) b[j] = Bs[k * 128 + cg + 16 * j];
        #pragma unroll
        for (int i = 0; i < 8; i++)
            #pragma unroll
            for (int j = 0; j < 8; j++) acc[i][j] += a[i] * b[j];
    }
    size_t gb = (size_t)rb * 128 * CC;
    #pragma unroll
    for (int i = 0; i < 8; i++)
        #pragma unroll
        for (int j = 0; j < 8; j++) {
            size_t idx = gb + (size_t)(8 * rg + i) * CC + cg + 16 * j;
            float v = acc[i][j];
            __nv_bfloat16 h = __float2bfloat16(v);
            g_Ghi[idx] = h;
            g_Glo[idx] = __float2bfloat16(v - __bfloat162float(h));
        }
}

// ---------------- main: mma.sync bf16 split GEMM + fused epilogue ---------
// smem: 4 tiles x 32KB (Ahi, Alo, Bhi, Blo), 256B rows, chunk-XOR swizzle.
__global__ void __launch_bounds__(256) k_main(const float* __restrict__ Ast,
                                              const float* __restrict__ Mm,
                                              float* __restrict__ out) {
    extern __shared__ char smem[];
    int tid = threadIdx.x, wid = tid >> 5, lane = tid & 31;
    int ct = blockIdx.x, rt = blockIdx.y, b = blockIdx.z;

    // ---- load 4 bf16 tiles (row-major [128][128]) into swizzled smem ----
    const __nv_bfloat16* srcs[4] = {
        g_Ghi + ((size_t)(b * NN + rt * 128)) * CC,
        g_Glo + ((size_t)(b * NN + rt * 128)) * CC,
        g_Hhi + ((size_t)(b * NN + ct * 128)) * CC,
        g_Hlo + ((size_t)(b * NN + ct * 128)) * CC};
    #pragma unroll
    for (int t = 0; t < 4; t++) {
        const uint4* src = (const uint4*)srcs[t];
        char* dst = smem + t * 32768;
        #pragma unroll
        for (int it = 0; it < 8; it++) {
            int idx = it * 256 + tid;
            int m = idx >> 4, c = idx & 15;
            uint4 v = src[idx];
            *(uint4*)(dst + m * 256 + ((c ^ (m & 7)) << 4)) = v;
        }
    }
    __syncthreads();

    uint32_t sm = smem_u32(smem);
    int wm = wid >> 2, wn = wid & 3;          // warp tile: 64(m) x 32(n)
    int mo = wm * 64, no = wn * 32;
    int lr = lane & 15, cb = lane >> 4, l7 = lane & 7;

    uint32_t rowA[4], rowB[2];
    #pragma unroll
    for (int i = 0; i < 4; i++) rowA[i] = (uint32_t)(mo + i * 16 + lr) * 256u;
    #pragma unroll
    for (int j = 0; j < 2; j++) rowB[j] = (uint32_t)(no + j * 16 + lr) * 256u;

    float acc[4][4][4];
    #pragma unroll
    for (int i = 0; i < 4; i++)
        #pragma unroll
        for (int j = 0; j < 4; j++)
            #pragma unroll
            for (int q = 0; q < 4; q++) acc[i][j][q] = 0.f;

    // passes: hi*hi, hi*lo, lo*hi
    #pragma unroll
    for (int p = 0; p < 3; p++) {
        uint32_t Ab = sm + ((p == 2) ? 32768u : 0u);
        uint32_t Bb = sm + ((p == 1) ? 98304u : 65536u);
        #pragma unroll
        for (int ks = 0; ks < 8; ks++) {
            uint32_t sw = (uint32_t)(((2 * ks + cb) ^ l7) << 4);
            uint32_t a[4][4], bf[2][4];
            #pragma unroll
            for (int i = 0; i < 4; i++)
                LDSM_X4(a[i][0], a[i][1], a[i][2], a[i][3], Ab + rowA[i] + sw);
            #pragma unroll
            for (int j = 0; j < 2; j++)
                LDSM_X4(bf[j][0], bf[j][1], bf[j][2], bf[j][3], Bb + rowB[j] + sw);
            #pragma unroll
            for (int i = 0; i < 4; i++)
                #pragma unroll
                for (int j = 0; j < 4; j++)
                    MMA16816(acc[i][j], a[i], bf[j >> 1][j & 1], bf[j >> 1][2 + (j & 1)]);
        }
    }

    // ---- epilogue: bias + mask + diag + exp + rowsum + STG ----
    size_t obase = (size_t)b * NN * NN;
    int q = lane >> 2, qq = (lane & 3) * 2;
    int gr0 = rt * 128 + mo;
    int gc0 = ct * 128 + no;

    #pragma unroll
    for (int i = 0; i < 4; i++) {
        int r1 = gr0 + i * 16 + q, r2 = r1 + 8;
        float s1 = 0.f, s2 = 0.f;
        #pragma unroll
        for (int j = 0; j < 4; j++) {
            int c = gc0 + j * 8 + qq;
            float2 a1 = *(const float2*)(Ast + (size_t)r1 * NN + c);
            float2 m1 = *(const float2*)(Mm  + (size_t)r1 * NN + c);
            float2 a2 = *(const float2*)(Ast + (size_t)r2 * NN + c);
            float2 m2 = *(const float2*)(Mm  + (size_t)r2 * NN + c);
            float2 e1, e2;
            e1.x = (m1.x > 0.f && c     != r1) ? __expf(acc[i][j][0] + a1.x) : 0.f;
            e1.y = (m1.y > 0.f && c + 1 != r1) ? __expf(acc[i][j][1] + a1.y) : 0.f;
            e2.x = (m2.x > 0.f && c     != r2) ? __expf(acc[i][j][2] + a2.x) : 0.f;
            e2.y = (m2.y > 0.f && c + 1 != r2) ? __expf(acc[i][j][3] + a2.y) : 0.f;
            *(float2*)(out + obase + (size_t)r1 * NN + c) = e1;
            *(float2*)(out + obase + (size_t)r2 * NN + c) = e2;
            s1 += e1.x + e1.y;
            s2 += e2.x + e2.y;
        }
        // reduce over the quad (lanes sharing the same row)
        #pragma unroll
        for (int o = 1; o < 4; o <<= 1) {
            s1 += __shfl_xor_sync(0xffffffffu, s1, o);
            s2 += __shfl_xor_sync(0xffffffffu, s2, o);
        }
        if ((lane & 3) == 0) {
            g_part[((size_t)(b * NN) + r1) * 64 + ct * 4 + wn] = s1;
            g_part[((size_t)(b * NN) + r2) * 64 + ct * 4 + wn] = s2;
        }
    }
}

// ---------------- 1/rowsum ----------------
__global__ void k_inv() {
    int r = blockIdx.x * blockDim.x + threadIdx.x;
    float s = 0.f;
    #pragma unroll
    for (int t = 0; t < 64; t++) s += g_part[(size_t)r * 64 + t];
    g_inv[r] = 1.0f / s;
}

// ---------------- normalize in place ----------------
__global__ void k_norm(float* __restrict__ out) {
    size_t idx4 = (size_t)blockIdx.x * blockDim.x + threadIdx.x;
    size_t row = idx4 >> 9;
    float inv = g_inv[row];
    float4 v = ((float4*)out)[idx4];
    v.x *= inv; v.y *= inv; v.z *= inv; v.w *= inv;
    ((float4*)out)[idx4] = v;
}

// ---------------- launch ----------------
extern "C" void kernel_launch(void* const* d_in, const int* in_sizes, int n_in,
                              void* d_out, int out_size) {
    const float* H   = (const float*)d_in[0];
    const float* Ast = (const float*)d_in[1];
    const float* Mm  = (const float*)d_in[2];
    const float* Wq  = (const float*)d_in[3];
    const float* Wk  = (const float*)d_in[4];
    float* out = (float*)d_out;

    static bool attr_done = false;
    if (!attr_done) {
        cudaFuncSetAttribute(k_G,    cudaFuncAttributeMaxDynamicSharedMemorySize, 131072);
        cudaFuncSetAttribute(k_main, cudaFuncAttributeMaxDynamicSharedMemorySize, 131072);
        attr_done = true;
    }

    k_wsym<<<CC, CC>>>(Wq, Wk);
    k_splitH<<<(BB * NN * CC / 4) / 256, 256>>>(H);
    k_G<<<(BB * NN) / 128, 256, 131072>>>(H);
    {
        dim3 grid(NN / 128, NN / 128, BB);
        k_main<<<grid, 256, 131072>>>(Ast, Mm, out);
    }
    k_inv<<<(BB * NN) / 256, 256>>>();
    k_norm<<<(BB * NN * NN / 4) / 256, 256>>>(out);
}

// round 4
// speedup vs baseline: 5.1955x; 1.5954x over previous
#include <cuda_runtime.h>
#include <cuda_fp16.h>
#include <math.h>
#include <stdint.h>

#define BB 16
#define NN 2048
#define CC 128

// ---------------- device scratch ----------------
__device__ float  g_Wsym[CC * CC];
__device__ __half g_Gh[BB * NN * CC];        // 8 MB
__device__ __half g_Hh[BB * NN * CC];        // 8 MB
__device__ float  g_bias[(size_t)NN * NN];   // 16 MB  combined mask+diag+A_stat
__device__ float  g_part[(size_t)BB * NN * 64];
__device__ float  g_inv[BB * NN];

// ---------------- helpers ----------------
__device__ __forceinline__ uint32_t smem_u32(const void* p) {
    uint32_t a;
    asm("{ .reg .u64 t; cvta.to.shared.u64 t, %1; cvt.u32.u64 %0, t; }" : "=r"(a) : "l"(p));
    return a;
}
__device__ __forceinline__ void cpasync16(uint32_t s, const void* g) {
    asm volatile("cp.async.cg.shared.global [%0], [%1], 16;" :: "r"(s), "l"(g));
}
#define CP_COMMIT() asm volatile("cp.async.commit_group;" ::: "memory")
#define CP_WAIT0()  asm volatile("cp.async.wait_group 0;" ::: "memory")

#define LDSM_X4(r0, r1, r2, r3, addr) \
    asm volatile("ldmatrix.sync.aligned.m8n8.x4.shared.b16 {%0,%1,%2,%3}, [%4];" \
        : "=r"(r0), "=r"(r1), "=r"(r2), "=r"(r3) : "r"(addr))

#define MMA16816(d, a, b0, b1) \
    asm volatile("mma.sync.aligned.m16n8k16.row.col.f32.f16.f16.f32 " \
        "{%0,%1,%2,%3}, {%4,%5,%6,%7}, {%8,%9}, {%0,%1,%2,%3};" \
        : "+f"((d)[0]), "+f"((d)[1]), "+f"((d)[2]), "+f"((d)[3]) \
        : "r"((a)[0]), "r"((a)[1]), "r"((a)[2]), "r"((a)[3]), "r"(b0), "r"(b1))

// ---------------- W_sym ----------------
__global__ void k_wsym(const float* __restrict__ Wq, const float* __restrict__ Wk) {
    int k = blockIdx.x, c = threadIdx.x;
    float a1 = 0.f, a2 = 0.f;
    for (int e = 0; e < CC; e++) {
        a1 += Wq[e * CC + k] * Wk[e * CC + c];
        a2 += Wk[e * CC + k] * Wq[e * CC + c];
    }
    g_Wsym[k * CC + c] = (0.5f / (sqrtf(128.0f) * 1.5f)) * (a1 + a2);
}

// ---------------- H -> fp16 ----------------
__global__ void k_splitH(const float* __restrict__ H) {
    size_t i = ((size_t)blockIdx.x * blockDim.x + threadIdx.x) * 4;
    float4 v = *(const float4*)(H + i);
    __half2* dst = (__half2*)(g_Hh + i);
    dst[0] = __floats2half2_rn(v.x, v.y);
    dst[1] = __floats2half2_rn(v.z, v.w);
}

// ---------------- combined bias: (m==n || M<=0) ? -1e30 : A_stat ----------
__global__ void k_bias(const float* __restrict__ Ast, const float* __restrict__ Mm) {
    size_t idx4 = (size_t)blockIdx.x * blockDim.x + threadIdx.x;
    int n = (int)(idx4 >> 9);
    int mb = (int)(idx4 & 511) * 4;
    float4 a = ((const float4*)Ast)[idx4];
    float4 m = ((const float4*)Mm)[idx4];
    float4 o;
    o.x = (m.x <= 0.f || mb + 0 == n) ? -1e30f : a.x;
    o.y = (m.y <= 0.f || mb + 1 == n) ? -1e30f : a.y;
    o.z = (m.z <= 0.f || mb + 2 == n) ? -1e30f : a.z;
    o.w = (m.w <= 0.f || mb + 3 == n) ? -1e30f : a.w;
    ((float4*)g_bias)[idx4] = o;
}

// ---------------- G = H @ W_sym -> fp16 ----------------
__device__ __forceinline__ int fxor(int k) { return ((k >> 2) ^ ((k & 3) << 3)); }

__global__ void __launch_bounds__(256) k_G(const float* __restrict__ H) {
    extern __shared__ float smf[];
    float* As = smf;
    float* Bs = smf + 128 * 128;
    int rb = blockIdx.x, tid = threadIdx.x;
    const float* Hp = H + (size_t)rb * 128 * CC;
    #pragma unroll
    for (int it = 0; it < 16; it++) {
        int flat = it * 256 + tid, m = flat >> 5, k4 = flat & 31;
        float4 v = *(const float4*)(Hp + m * CC + 4 * k4);
        As[(4 * k4 + 0) * 128 + (m ^ (k4 ^ 0 ))] = v.x;
        As[(4 * k4 + 1) * 128 + (m ^ (k4 ^ 8 ))] = v.y;
        As[(4 * k4 + 2) * 128 + (m ^ (k4 ^ 16))] = v.z;
        As[(4 * k4 + 3) * 128 + (m ^ (k4 ^ 24))] = v.w;
    }
    #pragma unroll
    for (int it = 0; it < 16; it++) {
        int flat = it * 256 + tid, k = flat >> 5, c4 = flat & 31;
        *(float4*)(Bs + k * 128 + 4 * c4) = *(const float4*)(g_Wsym + k * CC + 4 * c4);
    }
    __syncthreads();
    int rg = tid >> 4, cg = tid & 15;
    float acc[8][8];
    #pragma unroll
    for (int i = 0; i < 8; i++)
        #pragma unroll
        for (int j = 0; j < 8; j++) acc[i][j] = 0.f;
    #pragma unroll 4
    for (int k = 0; k < 128; k++) {
        int f = fxor(k);
        float a[8], b[8];
        #pragma unroll
        for (int i = 0; i < 8; i++) a[i] = As[k * 128 + ((8 * rg + i) ^ f)];
        #pragma unroll
        for (int j = 0; j < 8; j++) b[j] = Bs[k * 128 + cg + 16 * j];
        #pragma unroll
        for (int i = 0; i < 8; i++)
            #pragma unroll
            for (int j = 0; j < 8; j++) acc[i][j] += a[i] * b[j];
    }
    size_t gb = (size_t)rb * 128 * CC;
    #pragma unroll
    for (int i = 0; i < 8; i++)
        #pragma unroll
        for (int j = 0; j < 8; j++)
            g_Gh[gb + (size_t)(8 * rg + i) * CC + cg + 16 * j] = __float2half(acc[i][j]);
}

// ---------------- main: single-pass fp16 mma GEMM + fused epilogue --------
// smem: 2 tiles x 32KB (A=G rows, B=H rows), 256B rows, chunk-XOR swizzle.
__global__ void __launch_bounds__(256, 2) k_main(float* __restrict__ out) {
    extern __shared__ char smem[];
    int tid = threadIdx.x, wid = tid >> 5, lane = tid & 31;
    int ct = blockIdx.x, rt = blockIdx.y, b = blockIdx.z;
    uint32_t sm = smem_u32(smem);

    // ---- async-load 2 fp16 tiles into swizzled smem ----
    {
        const __half* Ap = g_Gh + ((size_t)(b * NN + rt * 128)) * CC;
        const __half* Bp = g_Hh + ((size_t)(b * NN + ct * 128)) * CC;
        #pragma unroll
        for (int it = 0; it < 8; it++) {
            int idx = it * 256 + tid;
            int m = idx >> 4, c = idx & 15;
            uint32_t dst = (uint32_t)(m * 256 + ((c ^ (m & 7)) << 4));
            cpasync16(sm + dst, Ap + (size_t)idx * 8);
            cpasync16(sm + 32768 + dst, Bp + (size_t)idx * 8);
        }
    }
    CP_COMMIT();
    CP_WAIT0();
    __syncthreads();

    int wm = wid >> 2, wn = wid & 3;      // warp tile 64(m) x 32(n)
    int mo = wm * 64, no = wn * 32;
    int lr = lane & 15, cb = lane >> 4, l7 = lane & 7;

    uint32_t rowA[4], rowB[2];
    #pragma unroll
    for (int i = 0; i < 4; i++) rowA[i] = sm + (uint32_t)(mo + i * 16 + lr) * 256u;
    #pragma unroll
    for (int j = 0; j < 2; j++) rowB[j] = sm + 32768u + (uint32_t)(no + j * 16 + lr) * 256u;

    float acc[4][4][4];
    #pragma unroll
    for (int i = 0; i < 4; i++)
        #pragma unroll
        for (int j = 0; j < 4; j++)
            #pragma unroll
            for (int q = 0; q < 4; q++) acc[i][j][q] = 0.f;

    #pragma unroll
    for (int ks = 0; ks < 8; ks++) {
        uint32_t sw = (uint32_t)(((2 * ks + cb) ^ l7) << 4);
        uint32_t a[4][4], bf[2][4];
        #pragma unroll
        for (int i = 0; i < 4; i++)
            LDSM_X4(a[i][0], a[i][1], a[i][2], a[i][3], rowA[i] + sw);
        #pragma unroll
        for (int j = 0; j < 2; j++)
            LDSM_X4(bf[j][0], bf[j][1], bf[j][2], bf[j][3], rowB[j] + sw);
        #pragma unroll
        for (int i = 0; i < 4; i++)
            #pragma unroll
            for (int j = 0; j < 4; j++)
                MMA16816(acc[i][j], a[i], bf[j >> 1][j & 1], bf[j >> 1][2 + (j & 1)]);
    }

    // ---- epilogue: +bias_eff, exp, rowsum, STG ----
    size_t obase = (size_t)b * NN * NN;
    int q = lane >> 2, qq = (lane & 3) * 2;
    int gr0 = rt * 128 + mo;
    int gc0 = ct * 128 + no;

    #pragma unroll
    for (int i = 0; i < 4; i++) {
        int r1 = gr0 + i * 16 + q, r2 = r1 + 8;
        const float* b1p = g_bias + (size_t)r1 * NN;
        const float* b2p = g_bias + (size_t)r2 * NN;
        float s1 = 0.f, s2 = 0.f;
        #pragma unroll
        for (int j = 0; j < 4; j++) {
            int c = gc0 + j * 8 + qq;
            float2 bb1 = *(const float2*)(b1p + c);
            float2 bb2 = *(const float2*)(b2p + c);
            float2 e1, e2;
            e1.x = __expf(acc[i][j][0] + bb1.x);
            e1.y = __expf(acc[i][j][1] + bb1.y);
            e2.x = __expf(acc[i][j][2] + bb2.x);
            e2.y = __expf(acc[i][j][3] + bb2.y);
            *(float2*)(out + obase + (size_t)r1 * NN + c) = e1;
            *(float2*)(out + obase + (size_t)r2 * NN + c) = e2;
            s1 += e1.x + e1.y;
            s2 += e2.x + e2.y;
        }
        #pragma unroll
        for (int o = 1; o < 4; o <<= 1) {
            s1 += __shfl_xor_sync(0xffffffffu, s1, o);
            s2 += __shfl_xor_sync(0xffffffffu, s2, o);
        }
        if ((lane & 3) == 0) {
            g_part[((size_t)(b * NN) + r1) * 64 + ct * 4 + wn] = s1;
            g_part[((size_t)(b * NN) + r2) * 64 + ct * 4 + wn] = s2;
        }
    }
}

// ---------------- 1/rowsum ----------------
__global__ void k_inv() {
    int r = blockIdx.x * blockDim.x + threadIdx.x;
    float s = 0.f;
    #pragma unroll
    for (int t = 0; t < 64; t++) s += g_part[(size_t)r * 64 + t];
    g_inv[r] = 1.0f / s;
}

// ---------------- normalize in place ----------------
__global__ void k_norm(float* __restrict__ out) {
    size_t idx4 = (size_t)blockIdx.x * blockDim.x + threadIdx.x;
    size_t row = idx4 >> 9;
    float inv = g_inv[row];
    float4 v = ((float4*)out)[idx4];
    v.x *= inv; v.y *= inv; v.z *= inv; v.w *= inv;
    ((float4*)out)[idx4] = v;
}

// ---------------- launch ----------------
extern "C" void kernel_launch(void* const* d_in, const int* in_sizes, int n_in,
                              void* d_out, int out_size) {
    const float* H   = (const float*)d_in[0];
    const float* Ast = (const float*)d_in[1];
    const float* Mm  = (const float*)d_in[2];
    const float* Wq  = (const float*)d_in[3];
    const float* Wk  = (const float*)d_in[4];
    float* out = (float*)d_out;

    static bool attr_done = false;
    if (!attr_done) {
        cudaFuncSetAttribute(k_G,    cudaFuncAttributeMaxDynamicSharedMemorySize, 131072);
        cudaFuncSetAttribute(k_main, cudaFuncAttributeMaxDynamicSharedMemorySize, 65536);
        attr_done = true;
    }

    k_wsym<<<CC, CC>>>(Wq, Wk);
    k_splitH<<<(BB * NN * CC / 4) / 256, 256>>>(H);
    k_bias<<<((size_t)NN * NN / 4) / 256, 256>>>(Ast, Mm);
    k_G<<<(BB * NN) / 128, 256, 131072>>>(H);
    {
        dim3 grid(NN / 128, NN / 128, BB);
        k_main<<<grid, 256, 65536>>>(out);
    }
    k_inv<<<(BB * NN) / 256, 256>>>();
    k_norm<<<(BB * NN * NN / 4) / 256, 256>>>(out);
}

// round 5
// speedup vs baseline: 5.7217x; 1.1013x over previous
#include <cuda_runtime.h>
#include <cuda_fp16.h>
#include <math.h>
#include <stdint.h>

#define BB 16
#define NN 2048
#define CC 128

// ---------------- device scratch ----------------
__device__ __half g_WsymH[CC * CC];          // 32 KB fp16, row-major [d][c]
__device__ __half g_Hh[BB * NN * CC];        // 8 MB fp16
__device__ float  g_bias[(size_t)NN * NN];   // 16 MB combined mask+diag+A_stat

// ---------------- helpers ----------------
__device__ __forceinline__ uint32_t smem_u32(const void* p) {
    uint32_t a;
    asm("{ .reg .u64 t; cvta.to.shared.u64 t, %1; cvt.u32.u64 %0, t; }" : "=r"(a) : "l"(p));
    return a;
}
__device__ __forceinline__ void cpasync16(uint32_t s, const void* g) {
    asm volatile("cp.async.cg.shared.global [%0], [%1], 16;" :: "r"(s), "l"(g));
}
#define CP_COMMIT() asm volatile("cp.async.commit_group;" ::: "memory")
#define CP_WAIT1()  asm volatile("cp.async.wait_group 1;" ::: "memory")

#define LDSM_X4(r0, r1, r2, r3, addr) \
    asm volatile("ldmatrix.sync.aligned.m8n8.x4.shared.b16 {%0,%1,%2,%3}, [%4];" \
        : "=r"(r0), "=r"(r1), "=r"(r2), "=r"(r3) : "r"(addr))

#define MMA16816(d, a, b0, b1) \
    asm volatile("mma.sync.aligned.m16n8k16.row.col.f32.f16.f16.f32 " \
        "{%0,%1,%2,%3}, {%4,%5,%6,%7}, {%8,%9}, {%0,%1,%2,%3};" \
        : "+f"((d)[0]), "+f"((d)[1]), "+f"((d)[2]), "+f"((d)[3]) \
        : "r"((a)[0]), "r"((a)[1]), "r"((a)[2]), "r"((a)[3]), "r"(b0), "r"(b1))

// ---------------- W_sym (fp32 compute, fp16 store) ----------------
__global__ void k_wsym(const float* __restrict__ Wq, const float* __restrict__ Wk) {
    int k = blockIdx.x, c = threadIdx.x;
    float a1 = 0.f, a2 = 0.f;
    for (int e = 0; e < CC; e++) {
        a1 += Wq[e * CC + k] * Wk[e * CC + c];
        a2 += Wk[e * CC + k] * Wq[e * CC + c];
    }
    g_WsymH[k * CC + c] = __float2half((0.5f / (sqrtf(128.0f) * 1.5f)) * (a1 + a2));
}

// ---------------- H -> fp16 ----------------
__global__ void k_splitH(const float* __restrict__ H) {
    size_t i = ((size_t)blockIdx.x * blockDim.x + threadIdx.x) * 4;
    float4 v = *(const float4*)(H + i);
    __half2* dst = (__half2*)(g_Hh + i);
    dst[0] = __floats2half2_rn(v.x, v.y);
    dst[1] = __floats2half2_rn(v.z, v.w);
}

// ---------------- combined bias ----------------
__global__ void k_bias(const float* __restrict__ Ast, const float* __restrict__ Mm) {
    size_t idx4 = (size_t)blockIdx.x * blockDim.x + threadIdx.x;
    int n = (int)(idx4 >> 9);
    int mb = (int)(idx4 & 511) * 4;
    float4 a = ((const float4*)Ast)[idx4];
    float4 m = ((const float4*)Mm)[idx4];
    float4 o;
    o.x = (m.x <= 0.f || mb + 0 == n) ? -1e30f : a.x;
    o.y = (m.y <= 0.f || mb + 1 == n) ? -1e30f : a.y;
    o.z = (m.z <= 0.f || mb + 2 == n) ? -1e30f : a.z;
    o.w = (m.w <= 0.f || mb + 3 == n) ? -1e30f : a.w;
    ((float4*)g_bias)[idx4] = o;
}

// ---------------- persistent main ----------------
// CTA = (rt, b). smem: bufA 32K | bufB0 32K | bufB1 32K | rowsum 2K | invs 512B
// Phase 1: G = H_rt @ Wsym (tensor), G frags -> bufA (overwrite)
// Phase 2: loop ct: GEMM G @ H_ct^T, epilogue exp + rowsum accumulation
// Phase 3: invs, in-place renormalization of own 1MB block.
__global__ void __launch_bounds__(256, 2) k_main(float* __restrict__ out) {
    extern __shared__ char smem[];
    uint32_t sm = smem_u32(smem);
    float* rowsum = (float*)(smem + 98304);   // [128][4]
    float* invs   = (float*)(smem + 98304 + 2048);
    int tid = threadIdx.x, wid = tid >> 5, lane = tid & 31;
    int rt = blockIdx.x, b = blockIdx.y;

    // zero rowsum slots
    ((float2*)rowsum)[tid] = make_float2(0.f, 0.f);

    const __half* Hrt = g_Hh + ((size_t)(b * NN + rt * 128)) * CC;

    // group1: H_rt -> bufA, Wsym -> bufB0
    #pragma unroll
    for (int it = 0; it < 8; it++) {
        int idx = it * 256 + tid;
        int m = idx >> 4, c = idx & 15;
        uint32_t dst = (uint32_t)(m * 256 + ((c ^ (m & 7)) << 4));
        cpasync16(sm + dst, Hrt + (size_t)idx * 8);
        cpasync16(sm + 32768 + dst, g_WsymH + idx * 8);
    }
    CP_COMMIT();
    // group2: ct=0 -> bufB1
    {
        const __half* Bp = g_Hh + ((size_t)(b * NN + 0 * 128)) * CC;
        #pragma unroll
        for (int it = 0; it < 8; it++) {
            int idx = it * 256 + tid;
            int m = idx >> 4, c = idx & 15;
            uint32_t dst = (uint32_t)(m * 256 + ((c ^ (m & 7)) << 4));
            cpasync16(sm + 65536 + dst, Bp + (size_t)idx * 8);
        }
    }
    CP_COMMIT();

    int wm = wid >> 2, wn = wid & 3;          // warp tile 64(m) x 32(n)
    int mo = wm * 64, no = wn * 32;
    int lr = lane & 15, cb = lane >> 4, l7 = lane & 7;
    int q = lane >> 2, qq = (lane & 3) * 2;

    uint32_t rowAoff[4], rowBoff[2];
    #pragma unroll
    for (int i = 0; i < 4; i++) rowAoff[i] = (uint32_t)(mo + i * 16 + lr) * 256u;
    #pragma unroll
    for (int j = 0; j < 2; j++) rowBoff[j] = (uint32_t)(no + j * 16 + lr) * 256u;

    float acc[4][4][4];

    // ---- Phase 1: G tile ----
    CP_WAIT1();      // group1 done (group2 may pend)
    __syncthreads();
    #pragma unroll
    for (int i = 0; i < 4; i++)
        #pragma unroll
        for (int j = 0; j < 4; j++)
            #pragma unroll
            for (int p = 0; p < 4; p++) acc[i][j][p] = 0.f;
    #pragma unroll
    for (int ks = 0; ks < 8; ks++) {
        uint32_t sw = (uint32_t)(((2 * ks + cb) ^ l7) << 4);
        uint32_t a[4][4], bf[2][4];
        #pragma unroll
        for (int i = 0; i < 4; i++)
            LDSM_X4(a[i][0], a[i][1], a[i][2], a[i][3], sm + rowAoff[i] + sw);
        #pragma unroll
        for (int j = 0; j < 2; j++)
            LDSM_X4(bf[j][0], bf[j][1], bf[j][2], bf[j][3], sm + 32768u + rowBoff[j] + sw);
        #pragma unroll
        for (int i = 0; i < 4; i++)
            #pragma unroll
            for (int j = 0; j < 4; j++)
                MMA16816(acc[i][j], a[i], bf[j >> 1][j & 1], bf[j >> 1][2 + (j & 1)]);
    }
    __syncthreads();   // everyone done reading bufA / Wsym

    // store G fragments into bufA (fp16, swizzled A layout)
    #pragma unroll
    for (int i = 0; i < 4; i++) {
        int r1 = mo + i * 16 + q;
        #pragma unroll
        for (int j = 0; j < 4; j++) {
            int c = no + j * 8 + qq;
            uint32_t ch = (uint32_t)(c >> 3);
            uint32_t off1 = (uint32_t)r1 * 256u + (((ch ^ ((uint32_t)r1 & 7)) << 4)) + (uint32_t)(c & 7) * 2u;
            int r2 = r1 + 8;
            uint32_t off2 = (uint32_t)r2 * 256u + (((ch ^ ((uint32_t)r2 & 7)) << 4)) + (uint32_t)(c & 7) * 2u;
            __half2 v1 = __floats2half2_rn(acc[i][j][0], acc[i][j][1]);
            __half2 v2 = __floats2half2_rn(acc[i][j][2], acc[i][j][3]);
            *(__half2*)(smem + off1) = v1;
            *(__half2*)(smem + off2) = v2;
        }
    }
    // prefetch ct=1 -> bufB0 (Wsym dead now)
    {
        const __half* Bp = g_Hh + ((size_t)(b * NN + 1 * 128)) * CC;
        #pragma unroll
        for (int it = 0; it < 8; it++) {
            int idx = it * 256 + tid;
            int m = idx >> 4, c = idx & 15;
            uint32_t dst = (uint32_t)(m * 256 + ((c ^ (m & 7)) << 4));
            cpasync16(sm + 32768 + dst, Bp + (size_t)idx * 8);
        }
    }
    CP_COMMIT();   // group3
    __syncthreads();   // G stores visible

    // ---- Phase 2: ct loop ----
    size_t obase = (size_t)b * NN * NN;
    int gr0 = rt * 128 + mo;

    #pragma unroll 1
    for (int ct = 0; ct < 16; ct++) {
        uint32_t Bb = sm + 32768u + (uint32_t)(((ct & 1) ^ 1) << 15);   // even->bufB1, odd->bufB0
        CP_WAIT1();
        __syncthreads();

        #pragma unroll
        for (int i = 0; i < 4; i++)
            #pragma unroll
            for (int j = 0; j < 4; j++)
                #pragma unroll
                for (int p = 0; p < 4; p++) acc[i][j][p] = 0.f;
        #pragma unroll
        for (int ks = 0; ks < 8; ks++) {
            uint32_t sw = (uint32_t)(((2 * ks + cb) ^ l7) << 4);
            uint32_t a[4][4], bf[2][4];
            #pragma unroll
            for (int i = 0; i < 4; i++)
                LDSM_X4(a[i][0], a[i][1], a[i][2], a[i][3], sm + rowAoff[i] + sw);
            #pragma unroll
            for (int j = 0; j < 2; j++)
                LDSM_X4(bf[j][0], bf[j][1], bf[j][2], bf[j][3], Bb + rowBoff[j] + sw);
            #pragma unroll
            for (int i = 0; i < 4; i++)
                #pragma unroll
                for (int j = 0; j < 4; j++)
                    MMA16816(acc[i][j], a[i], bf[j >> 1][j & 1], bf[j >> 1][2 + (j & 1)]);
        }
        __syncthreads();   // done reading this B slot

        // prefetch ct+2 into the slot just freed (empty-commit keeps group count)
        if (ct + 2 < 16) {
            const __half* Bp = g_Hh + ((size_t)(b * NN + (ct + 2) * 128)) * CC;
            #pragma unroll
            for (int it = 0; it < 8; it++) {
                int idx = it * 256 + tid;
                int m = idx >> 4, c = idx & 15;
                uint32_t dst = (uint32_t)(m * 256 + ((c ^ (m & 7)) << 4));
                cpasync16(Bb + dst, Bp + (size_t)idx * 8);
            }
        }
        CP_COMMIT();

        // epilogue
        int gc0 = ct * 128 + no;
        #pragma unroll
        for (int i = 0; i < 4; i++) {
            int lrow = mo + i * 16 + q;
            int r1 = rt * 128 + lrow, r2 = r1 + 8;
            const float* b1p = g_bias + (size_t)r1 * NN;
            const float* b2p = g_bias + (size_t)r2 * NN;
            float s1 = 0.f, s2 = 0.f;
            #pragma unroll
            for (int j = 0; j < 4; j++) {
                int c = gc0 + j * 8 + qq;
                float2 bb1 = *(const float2*)(b1p + c);
                float2 bb2 = *(const float2*)(b2p + c);
                float2 e1, e2;
                e1.x = __expf(acc[i][j][0] + bb1.x);
                e1.y = __expf(acc[i][j][1] + bb1.y);
                e2.x = __expf(acc[i][j][2] + bb2.x);
                e2.y = __expf(acc[i][j][3] + bb2.y);
                *(float2*)(out + obase + (size_t)r1 * NN + c) = e1;
                *(float2*)(out + obase + (size_t)r2 * NN + c) = e2;
                s1 += e1.x + e1.y;
                s2 += e2.x + e2.y;
            }
            #pragma unroll
            for (int o = 1; o < 4; o <<= 1) {
                s1 += __shfl_xor_sync(0xffffffffu, s1, o);
                s2 += __shfl_xor_sync(0xffffffffu, s2, o);
            }
            if ((lane & 3) == 0) {
                rowsum[lrow * 4 + wn] += s1;
                rowsum[(lrow + 8) * 4 + wn] += s2;
            }
        }
    }
    __syncthreads();

    // ---- Phase 3: invs + in-place renorm ----
    if (tid < 128) {
        float s = rowsum[tid * 4] + rowsum[tid * 4 + 1] + rowsum[tid * 4 + 2] + rowsum[tid * 4 + 3];
        invs[tid] = 1.0f / s;
    }
    __syncthreads();

    float4* ob4 = (float4*)(out + obase + (size_t)(rt * 128) * NN);
    #pragma unroll 4
    for (int idx = tid; idx < 128 * 512; idx += 256) {
        int row = idx >> 9;
        float inv = invs[row];
        float4 v = ob4[idx];
        v.x *= inv; v.y *= inv; v.z *= inv; v.w *= inv;
        ob4[idx] = v;
    }
}

// ---------------- launch ----------------
extern "C" void kernel_launch(void* const* d_in, const int* in_sizes, int n_in,
                              void* d_out, int out_size) {
    const float* H   = (const float*)d_in[0];
    const float* Ast = (const float*)d_in[1];
    const float* Mm  = (const float*)d_in[2];
    const float* Wq  = (const float*)d_in[3];
    const float* Wk  = (const float*)d_in[4];
    float* out = (float*)d_out;

    static bool attr_done = false;
    if (!attr_done) {
        cudaFuncSetAttribute(k_main, cudaFuncAttributeMaxDynamicSharedMemorySize, 101376);
        attr_done = true;
    }

    k_wsym<<<CC, CC>>>(Wq, Wk);
    k_splitH<<<(BB * NN * CC / 4) / 256, 256>>>(H);
    k_bias<<<((size_t)NN * NN / 4) / 256, 256>>>(Ast, Mm);
    {
        dim3 grid(NN / 128, BB);   // (rt, b)
        k_main<<<grid, 256, 101376>>>(out);
    }
}